// round 15
// baseline (speedup 1.0000x reference)
#include <cuda_runtime.h>
#include <cuda_fp16.h>
#include <math.h>
#include <stdint.h>

#define NN 50000
#define EE 800000
#define NHEADS 8
#define HIDD 32
#define FTOT 256   // NHEADS*HIDD, also IN_FEATS
#define NB 49      // scan blocks: 49*1024 >= NN
#define M1SPLIT 25088  // node split point: 196*128, 98*256

// ---------------- scratch (static device globals; no allocation) ----------------
__device__ __align__(16) __half g_featA[(size_t)NN * FTOT];  // layer0 GEMM out
__device__ __align__(16) __half g_featB[(size_t)NN * FTOT];  // layer1 GEMM out
__device__ __align__(16) __half g_hH[(size_t)NN * FTOT];     // agg8 out
__device__ __align__(16) __half g_WH[2][FTOT * FTOT];        // W0/W1 transposed fp16
__device__ __align__(16) __half g_W2H[HIDD * FTOT];          // W2 transposed fp16
__device__ __align__(16) float g_feat2[(size_t)NN * HIDD];
__device__ __align__(16) float g_elA[NN * NHEADS];
__device__ __align__(16) float g_erA[NN * NHEADS];
__device__ __align__(16) float g_elB[NN * NHEADS];
__device__ __align__(16) float g_erB[NN * NHEADS];
__device__ int g_count[NN];
__device__ int g_off[NN + 1];
__device__ int g_cursor[NN];
__device__ int g_srcs[EE];
__device__ int g_bsum[64];
__device__ int g_boff[64];

// ---------------- helpers ----------------
__device__ __forceinline__ uint32_t smem_u32(const void* p) {
    uint32_t a;
    asm("{ .reg .u64 t; cvta.to.shared.u64 t, %1; cvt.u32.u64 %0, t; }" : "=r"(a) : "l"(p));
    return a;
}
__device__ __forceinline__ void ldsm_x4(uint32_t addr, uint32_t& r0, uint32_t& r1,
                                        uint32_t& r2, uint32_t& r3) {
    asm volatile("ldmatrix.sync.aligned.m8n8.x4.shared.b16 {%0,%1,%2,%3}, [%4];"
                 : "=r"(r0), "=r"(r1), "=r"(r2), "=r"(r3) : "r"(addr));
}
__device__ __forceinline__ void mma_f16(float* d, const uint32_t* a, const uint32_t* b) {
    asm volatile(
        "mma.sync.aligned.m16n8k16.row.col.f32.f16.f16.f32 "
        "{%0,%1,%2,%3}, {%4,%5,%6,%7}, {%8,%9}, {%0,%1,%2,%3};"
        : "+f"(d[0]), "+f"(d[1]), "+f"(d[2]), "+f"(d[3])
        : "r"(a[0]), "r"(a[1]), "r"(a[2]), "r"(a[3]), "r"(b[0]), "r"(b[1]));
}
__device__ __forceinline__ uint32_t pack2h(float a, float b) {
    __half2 t = __floats2half2_rn(a, b);
    return *(uint32_t*)&t;
}
__device__ __forceinline__ float safe_exp(float x) {
    return __expf(fmaxf(x, -88.f));
}
__device__ __forceinline__ void loadA16(const float* p, uint32_t* d) {
    const float4* q = (const float4*)p;
    #pragma unroll
    for (int i = 0; i < 4; i++) {
        float4 v = q[i];
        d[2 * i]     = pack2h(v.x, v.y);
        d[2 * i + 1] = pack2h(v.z, v.w);
    }
}
__device__ __forceinline__ void loadA16(const __half* p, uint32_t* d) {
    uint4 a = ((const uint4*)p)[0];
    uint4 b = ((const uint4*)p)[1];
    d[0] = a.x; d[1] = a.y; d[2] = a.z; d[3] = a.w;
    d[4] = b.x; d[5] = b.y; d[6] = b.z; d[7] = b.w;
}
__device__ __forceinline__ void zeroA16(uint32_t* d) {
    #pragma unroll
    for (int q = 0; q < 8; q++) d[q] = 0u;
}

// ---------------- W transposes ----------------
__global__ void wtrans_kernel(const float* __restrict__ W, __half* __restrict__ Wt) {
    int n = blockIdx.x;
    int k = threadIdx.x;
    Wt[n * FTOT + k] = __float2half(W[(size_t)k * FTOT + n]);
}
__global__ void wtrans2_kernel(const float* __restrict__ W2, __half* __restrict__ W2t) {
    int n = blockIdx.x;
    int k = threadIdx.x;
    W2t[n * FTOT + k] = __float2half(W2[(size_t)k * HIDD + n]);
}

// ---------------- mma.sync fp16 GEMM ----------------
#define SP 40
#define TILE_H (128 * SP)
#define BUF_H (2 * TILE_H)
#define GEMM_SMEM (2 * BUF_H * 2)

template <typename TA>
__global__ void __launch_bounds__(256, 2)
mma_gemm_kernel(const TA* __restrict__ A, const __half* __restrict__ Wt,
                __half* __restrict__ C, const float* __restrict__ al,
                const float* __restrict__ ar, float* __restrict__ el,
                float* __restrict__ er, int M) {
    extern __shared__ __half2 smem_raw[];
    uint16_t* smem = (uint16_t*)smem_raw;
    const int tid = threadIdx.x;
    const int wid = tid >> 5;
    const int lane = tid & 31;
    const int rowBase = blockIdx.y * 128;
    const int colBase = blockIdx.x * 128;
    const int mbase = (wid >> 2) * 64;
    const int nbase = (wid & 3) * 32;

    float acc[4][4][4];
    #pragma unroll
    for (int i = 0; i < 4; i++)
        #pragma unroll
        for (int j = 0; j < 4; j++)
            #pragma unroll
            for (int q = 0; q < 4; q++) acc[i][j][q] = 0.f;

    const int arow = tid >> 1;
    const int akq  = (tid & 1) * 4;
    const __half* Brow = Wt + (size_t)(colBase + arow) * FTOT;

    uint32_t prawA[8], prawB[8];
    {
        int gr = rowBase + arow;
        if (gr < M) loadA16(A + (size_t)gr * FTOT + akq * 4, prawA);
        else zeroA16(prawA);
        loadA16(Brow + akq * 4, prawB);
    }

    for (int c = 0; c < 8; c++) {
        const int b = c & 1;
        uint16_t* As = smem + b * BUF_H;
        uint16_t* Bs = As + TILE_H;

        {
            uint4* da = (uint4*)(As + arow * SP + akq * 4);
            da[0] = make_uint4(prawA[0], prawA[1], prawA[2], prawA[3]);
            da[1] = make_uint4(prawA[4], prawA[5], prawA[6], prawA[7]);
            uint4* db = (uint4*)(Bs + arow * SP + akq * 4);
            db[0] = make_uint4(prawB[0], prawB[1], prawB[2], prawB[3]);
            db[1] = make_uint4(prawB[4], prawB[5], prawB[6], prawB[7]);
        }

        if (c < 7) {
            int gr = rowBase + arow;
            if (gr < M) loadA16(A + (size_t)gr * FTOT + (c + 1) * 32 + akq * 4, prawA);
            else zeroA16(prawA);
            loadA16(Brow + (c + 1) * 32 + akq * 4, prawB);
        }
        __syncthreads();

        const uint32_t as = smem_u32(As);
        const uint32_t bs = smem_u32(Bs);
        const int t = lane >> 3, r = lane & 7;
        #pragma unroll
        for (int ks = 0; ks < 2; ks++) {
            uint32_t Ah[4][4], Bh[4][2];
            const int a_row_off = (t & 1) * 8 + r;
            const int a_col = ks * 16 + (t >> 1) * 8;
            #pragma unroll
            for (int f = 0; f < 4; f++) {
                uint32_t off = ((mbase + f * 16 + a_row_off) * SP + a_col) * 2;
                ldsm_x4(as + off, Ah[f][0], Ah[f][1], Ah[f][2], Ah[f][3]);
            }
            const int b_row_off = (t >> 1) * 8 + r;
            const int b_col = ks * 16 + (t & 1) * 8;
            #pragma unroll
            for (int g = 0; g < 2; g++) {
                uint32_t off = ((nbase + g * 16 + b_row_off) * SP + b_col) * 2;
                ldsm_x4(bs + off, Bh[2 * g][0], Bh[2 * g][1], Bh[2 * g + 1][0], Bh[2 * g + 1][1]);
            }
            #pragma unroll
            for (int i = 0; i < 4; i++)
                #pragma unroll
                for (int j = 0; j < 4; j++)
                    mma_f16(acc[i][j], Ah[i], Bh[j]);
        }
    }

    const int rq = lane >> 2;
    const int cq = (lane & 3) * 2;
    const int hIdx = (colBase >> 5) + (wid & 3);
    float alv[4][2], arv[4][2];
    #pragma unroll
    for (int j = 0; j < 4; j++) {
        int d0 = hIdx * HIDD + j * 8 + cq;
        alv[j][0] = al[d0]; alv[j][1] = al[d0 + 1];
        arv[j][0] = ar[d0]; arv[j][1] = ar[d0 + 1];
    }
    #pragma unroll
    for (int i = 0; i < 4; i++) {
        int r0 = rowBase + mbase + i * 16 + rq;
        int r1 = r0 + 8;
        float sl0 = 0.f, sr0 = 0.f, sl1 = 0.f, sr1 = 0.f;
        #pragma unroll
        for (int j = 0; j < 4; j++) {
            int cc = colBase + nbase + j * 8 + cq;
            if (r0 < M) *(uint32_t*)(C + (size_t)r0 * FTOT + cc) = pack2h(acc[i][j][0], acc[i][j][1]);
            if (r1 < M) *(uint32_t*)(C + (size_t)r1 * FTOT + cc) = pack2h(acc[i][j][2], acc[i][j][3]);
            sl0 = fmaf(acc[i][j][0], alv[j][0], fmaf(acc[i][j][1], alv[j][1], sl0));
            sr0 = fmaf(acc[i][j][0], arv[j][0], fmaf(acc[i][j][1], arv[j][1], sr0));
            sl1 = fmaf(acc[i][j][2], alv[j][0], fmaf(acc[i][j][3], alv[j][1], sl1));
            sr1 = fmaf(acc[i][j][2], arv[j][0], fmaf(acc[i][j][3], arv[j][1], sr1));
        }
        #pragma unroll
        for (int d = 1; d <= 2; d <<= 1) {
            sl0 += __shfl_xor_sync(0xffffffffu, sl0, d);
            sr0 += __shfl_xor_sync(0xffffffffu, sr0, d);
            sl1 += __shfl_xor_sync(0xffffffffu, sl1, d);
            sr1 += __shfl_xor_sync(0xffffffffu, sr1, d);
        }
        if ((lane & 3) == 0) {
            if (r0 < M) { el[r0 * NHEADS + hIdx] = sl0; er[r0 * NHEADS + hIdx] = sr0; }
            if (r1 < M) { el[r1 * NHEADS + hIdx] = sl1; er[r1 * NHEADS + hIdx] = sr1; }
        }
    }
}

// ---------------- final-layer mma GEMM ----------------
#define FSP 40
#define FA_H (256 * FSP)
#define FB_H (32 * FSP)
#define FBUF_H (FA_H + FB_H)
#define FGEMM_SMEM (2 * FBUF_H * 2)

__global__ void __launch_bounds__(256, 2)
mma_final_kernel(const __half* __restrict__ A, const __half* __restrict__ W2t,
                 float* __restrict__ C, const float* __restrict__ al,
                 const float* __restrict__ ar, float* __restrict__ el,
                 float* __restrict__ er, int M) {
    extern __shared__ __half2 smem_raw[];
    uint16_t* smem = (uint16_t*)smem_raw;
    const int tid = threadIdx.x;
    const int wid = tid >> 5;
    const int lane = tid & 31;
    const int rowBase = blockIdx.y * 256;
    const int mbase = wid * 32;

    float acc[2][4][4];
    #pragma unroll
    for (int i = 0; i < 2; i++)
        #pragma unroll
        for (int j = 0; j < 4; j++)
            #pragma unroll
            for (int q = 0; q < 4; q++) acc[i][j][q] = 0.f;

    const int brow = tid >> 1;
    const int bsl  = (tid & 1) * 16;

    uint32_t prawA[16], prawB[8];
    {
        int gr = rowBase + tid;
        if (gr < M) {
            loadA16(A + (size_t)gr * FTOT, prawA);
            loadA16(A + (size_t)gr * FTOT + 16, prawA + 8);
        } else { zeroA16(prawA); zeroA16(prawA + 8); }
        if (tid < 64) loadA16(W2t + (size_t)brow * FTOT + bsl, prawB);
    }

    for (int c = 0; c < 8; c++) {
        const int b = c & 1;
        uint16_t* As = smem + b * FBUF_H;
        uint16_t* Bs = As + FA_H;

        {
            uint4* da = (uint4*)(As + tid * FSP);
            da[0] = make_uint4(prawA[0], prawA[1], prawA[2], prawA[3]);
            da[1] = make_uint4(prawA[4], prawA[5], prawA[6], prawA[7]);
            da[2] = make_uint4(prawA[8], prawA[9], prawA[10], prawA[11]);
            da[3] = make_uint4(prawA[12], prawA[13], prawA[14], prawA[15]);
            if (tid < 64) {
                uint4* db = (uint4*)(Bs + brow * FSP + bsl);
                db[0] = make_uint4(prawB[0], prawB[1], prawB[2], prawB[3]);
                db[1] = make_uint4(prawB[4], prawB[5], prawB[6], prawB[7]);
            }
        }

        if (c < 7) {
            int gr = rowBase + tid;
            const __half* Ab = A + (size_t)gr * FTOT + (c + 1) * 32;
            if (gr < M) { loadA16(Ab, prawA); loadA16(Ab + 16, prawA + 8); }
            else { zeroA16(prawA); zeroA16(prawA + 8); }
            if (tid < 64) loadA16(W2t + (size_t)brow * FTOT + (c + 1) * 32 + bsl, prawB);
        }
        __syncthreads();

        const uint32_t as = smem_u32(As);
        const uint32_t bs = smem_u32(Bs);
        const int t = lane >> 3, r = lane & 7;
        #pragma unroll
        for (int ks = 0; ks < 2; ks++) {
            uint32_t Ah[2][4], Bh[4][2];
            const int a_row_off = (t & 1) * 8 + r;
            const int a_col = ks * 16 + (t >> 1) * 8;
            #pragma unroll
            for (int f = 0; f < 2; f++) {
                uint32_t off = ((mbase + f * 16 + a_row_off) * FSP + a_col) * 2;
                ldsm_x4(as + off, Ah[f][0], Ah[f][1], Ah[f][2], Ah[f][3]);
            }
            const int b_row_off = (t >> 1) * 8 + r;
            const int b_col = ks * 16 + (t & 1) * 8;
            #pragma unroll
            for (int g = 0; g < 2; g++) {
                uint32_t off = ((g * 16 + b_row_off) * FSP + b_col) * 2;
                ldsm_x4(bs + off, Bh[2 * g][0], Bh[2 * g][1], Bh[2 * g + 1][0], Bh[2 * g + 1][1]);
            }
            #pragma unroll
            for (int i = 0; i < 2; i++)
                #pragma unroll
                for (int j = 0; j < 4; j++)
                    mma_f16(acc[i][j], Ah[i], Bh[j]);
        }
    }

    const int rq = lane >> 2;
    const int cq = (lane & 3) * 2;
    float alv[4][2], arv[4][2];
    #pragma unroll
    for (int j = 0; j < 4; j++) {
        int d0 = j * 8 + cq;
        alv[j][0] = al[d0]; alv[j][1] = al[d0 + 1];
        arv[j][0] = ar[d0]; arv[j][1] = ar[d0 + 1];
    }
    #pragma unroll
    for (int i = 0; i < 2; i++) {
        int r0 = rowBase + mbase + i * 16 + rq;
        int r1 = r0 + 8;
        float sl0 = 0.f, sr0 = 0.f, sl1 = 0.f, sr1 = 0.f;
        #pragma unroll
        for (int j = 0; j < 4; j++) {
            int cc = j * 8 + cq;
            if (r0 < M) *(float2*)(C + (size_t)r0 * HIDD + cc) = make_float2(acc[i][j][0], acc[i][j][1]);
            if (r1 < M) *(float2*)(C + (size_t)r1 * HIDD + cc) = make_float2(acc[i][j][2], acc[i][j][3]);
            sl0 = fmaf(acc[i][j][0], alv[j][0], fmaf(acc[i][j][1], alv[j][1], sl0));
            sr0 = fmaf(acc[i][j][0], arv[j][0], fmaf(acc[i][j][1], arv[j][1], sr0));
            sl1 = fmaf(acc[i][j][2], alv[j][0], fmaf(acc[i][j][3], alv[j][1], sl1));
            sr1 = fmaf(acc[i][j][2], arv[j][0], fmaf(acc[i][j][3], arv[j][1], sr1));
        }
        #pragma unroll
        for (int d = 1; d <= 2; d <<= 1) {
            sl0 += __shfl_xor_sync(0xffffffffu, sl0, d);
            sr0 += __shfl_xor_sync(0xffffffffu, sr0, d);
            sl1 += __shfl_xor_sync(0xffffffffu, sl1, d);
            sr1 += __shfl_xor_sync(0xffffffffu, sr1, d);
        }
        if ((lane & 3) == 0) {
            if (r0 < M) { el[r0] = sl0; er[r0] = sr0; }
            if (r1 < M) { el[r1] = sl1; er[r1] = sr1; }
        }
    }
}

// ---------------- CSR build ----------------
__global__ void hist_kernel(const int* __restrict__ dst, int* __restrict__ count) {
    int e = blockIdx.x * blockDim.x + threadIdx.x;
    if (e < EE) atomicAdd(&count[dst[e]], 1);
}

__global__ void scan1_kernel(const int* __restrict__ count, int* __restrict__ off,
                             int* __restrict__ bsum) {
    __shared__ int wsum[32];
    const int t = threadIdx.x;
    const int lane = t & 31, w = t >> 5;
    const int i = blockIdx.x * 1024 + t;
    int v = (i < NN) ? count[i] : 0;
    int incl = v;
    #pragma unroll
    for (int d = 1; d < 32; d <<= 1) {
        int x = __shfl_up_sync(0xffffffffu, incl, d);
        if (lane >= d) incl += x;
    }
    if (lane == 31) wsum[w] = incl;
    __syncthreads();
    if (w == 0) {
        int s = wsum[lane];
        #pragma unroll
        for (int d = 1; d < 32; d <<= 1) {
            int x = __shfl_up_sync(0xffffffffu, s, d);
            if (lane >= d) s += x;
        }
        wsum[lane] = s;
    }
    __syncthreads();
    int wpre = (w > 0) ? wsum[w - 1] : 0;
    if (i < NN) off[i] = wpre + incl - v;
    if (t == 0) bsum[blockIdx.x] = wsum[31];
}

__global__ void scan2_kernel(const int* __restrict__ bsum, int* __restrict__ boff,
                             int* __restrict__ off) {
    __shared__ int tmp[64];
    int t = threadIdx.x;
    int v = (t < NB) ? bsum[t] : 0;
    tmp[t] = v;
    __syncthreads();
    #pragma unroll
    for (int d = 1; d < 64; d <<= 1) {
        int x = (t >= d) ? tmp[t - d] : 0;
        __syncthreads();
        tmp[t] += x;
        __syncthreads();
    }
    if (t < NB) boff[t] = tmp[t] - v;
    if (t == 63) off[NN] = tmp[63];
}

__global__ void scan3_kernel(int* __restrict__ off, const int* __restrict__ boff,
                             int* __restrict__ cursor) {
    const int i = blockIdx.x * 1024 + threadIdx.x;
    if (i < NN) {
        int o = off[i] + boff[blockIdx.x];
        off[i] = o;
        cursor[i] = o;
    }
}

__global__ void scatter_kernel(const int* __restrict__ dst, const int* __restrict__ srcArr,
                               int* __restrict__ cursor, int* __restrict__ srcs) {
    int e = blockIdx.x * blockDim.x + threadIdx.x;
    if (e < EE) {
        int pos = atomicAdd(&cursor[dst[e]], 1);
        srcs[pos] = srcArr[e];
    }
}

// ---------------- per-node warp: SINGLE-PASS flash-style softmax + aggregate
__global__ void __launch_bounds__(256)
agg8_kernel(const __half* __restrict__ feat, const float* __restrict__ el,
            const float* __restrict__ er, const float* __restrict__ bias,
            __half* __restrict__ out, const int* __restrict__ off,
            const int* __restrict__ srcs, int nodeOff, int nodeCnt) {
    int warp = (blockIdx.x * blockDim.x + threadIdx.x) >> 5;
    if (warp >= nodeCnt) return;
    const int lane = threadIdx.x & 31;
    const int n = nodeOff + warp;
    const int s = off[n], epnd = off[n + 1];
    const int hl = lane & 7;
    const int eslot = lane >> 3;
    const int myh = lane >> 2;
    const float er_h = er[n * NHEADS + hl];
    const __half* fbase = feat + lane * 8;

    float mx = -INFINITY;
    float sm = 0.f;
    float acc[8];
    #pragma unroll
    for (int q = 0; q < 8; q++) acc[q] = 0.f;

    int i = s;
    for (; i + 8 <= epnd; i += 8) {
        int s0 = srcs[i + eslot];
        int s1 = srcs[i + 4 + eslot];
        float v0 = el[s0 * NHEADS + hl] + er_h;
        float v1 = el[s1 * NHEADS + hl] + er_h;
        v0 = v0 > 0.f ? v0 : 0.2f * v0;
        v1 = v1 > 0.f ? v1 : 0.2f * v1;
        float bm = fmaxf(v0, v1);
        bm = fmaxf(bm, __shfl_xor_sync(0xffffffffu, bm, 8));
        bm = fmaxf(bm, __shfl_xor_sync(0xffffffffu, bm, 16));
        float m2 = fmaxf(mx, bm);
        float scale = safe_exp(mx - m2);
        float c0 = safe_exp(v0 - m2);
        float c1 = safe_exp(v1 - m2);
        sm = sm * scale + c0 + c1;
        mx = m2;
        float cs = __shfl_sync(0xffffffffu, scale, myh);
        float c[8]; int se[8];
        #pragma unroll
        for (int e = 0; e < 4; e++) {
            c[e]      = __shfl_sync(0xffffffffu, c0, e * 8 + myh);
            c[e + 4]  = __shfl_sync(0xffffffffu, c1, e * 8 + myh);
            se[e]     = __shfl_sync(0xffffffffu, s0, e * 8);
            se[e + 4] = __shfl_sync(0xffffffffu, s1, e * 8);
        }
        uint4 raw[8];
        #pragma unroll
        for (int e = 0; e < 8; e++)
            raw[e] = *(const uint4*)(fbase + (size_t)se[e] * FTOT);
        #pragma unroll
        for (int q = 0; q < 8; q++) acc[q] *= cs;
        #pragma unroll
        for (int e = 0; e < 8; e++) {
            const __half2* hp = (const __half2*)&raw[e];
            #pragma unroll
            for (int q = 0; q < 4; q++) {
                float2 f = __half22float2(hp[q]);
                acc[q * 2]     = fmaf(c[e], f.x, acc[q * 2]);
                acc[q * 2 + 1] = fmaf(c[e], f.y, acc[q * 2 + 1]);
            }
        }
    }
    for (; i + 4 <= epnd; i += 4) {
        int esrc = srcs[i + eslot];
        float v = el[esrc * NHEADS + hl] + er_h;
        v = v > 0.f ? v : 0.2f * v;
        float bm = v;
        bm = fmaxf(bm, __shfl_xor_sync(0xffffffffu, bm, 8));
        bm = fmaxf(bm, __shfl_xor_sync(0xffffffffu, bm, 16));
        float m2 = fmaxf(mx, bm);
        float scale = safe_exp(mx - m2);
        float coef = safe_exp(v - m2);
        sm = sm * scale + coef;
        mx = m2;
        float cs = __shfl_sync(0xffffffffu, scale, myh);
        float c[4]; int se[4];
        #pragma unroll
        for (int e = 0; e < 4; e++) {
            c[e]  = __shfl_sync(0xffffffffu, coef, e * 8 + myh);
            se[e] = __shfl_sync(0xffffffffu, esrc, e * 8);
        }
        uint4 raw[4];
        #pragma unroll
        for (int e = 0; e < 4; e++)
            raw[e] = *(const uint4*)(fbase + (size_t)se[e] * FTOT);
        #pragma unroll
        for (int q = 0; q < 8; q++) acc[q] *= cs;
        #pragma unroll
        for (int e = 0; e < 4; e++) {
            const __half2* hp = (const __half2*)&raw[e];
            #pragma unroll
            for (int q = 0; q < 4; q++) {
                float2 f = __half22float2(hp[q]);
                acc[q * 2]     = fmaf(c[e], f.x, acc[q * 2]);
                acc[q * 2 + 1] = fmaf(c[e], f.y, acc[q * 2 + 1]);
            }
        }
    }
    for (; i < epnd; i++) {
        int srcT = srcs[i];
        float v = el[srcT * NHEADS + hl] + er_h;
        v = v > 0.f ? v : 0.2f * v;
        float m2 = fmaxf(mx, v);
        float scale = safe_exp(mx - m2);
        float coef = safe_exp(v - m2);
        sm = sm * scale + (eslot == 0 ? coef : 0.f);
        mx = m2;
        float cs = __shfl_sync(0xffffffffu, scale, myh);
        float c  = __shfl_sync(0xffffffffu, coef, myh);
        uint4 raw = *(const uint4*)(fbase + (size_t)srcT * FTOT);
        const __half2* hp = (const __half2*)&raw;
        #pragma unroll
        for (int q = 0; q < 8; q++) acc[q] *= cs;
        #pragma unroll
        for (int q = 0; q < 4; q++) {
            float2 f = __half22float2(hp[q]);
            acc[q * 2]     = fmaf(c, f.x, acc[q * 2]);
            acc[q * 2 + 1] = fmaf(c, f.y, acc[q * 2 + 1]);
        }
    }
    sm += __shfl_xor_sync(0xffffffffu, sm, 8);
    sm += __shfl_xor_sync(0xffffffffu, sm, 16);
    float inv = 1.0f / (sm + 1e-9f);
    float cinv = __shfl_sync(0xffffffffu, inv, myh);
    float4 b0 = *(const float4*)(bias + lane * 8);
    float4 b1 = *(const float4*)(bias + lane * 8 + 4);
    float o[8];
    o[0] = acc[0] * cinv + b0.x; o[1] = acc[1] * cinv + b0.y;
    o[2] = acc[2] * cinv + b0.z; o[3] = acc[3] * cinv + b0.w;
    o[4] = acc[4] * cinv + b1.x; o[5] = acc[5] * cinv + b1.y;
    o[6] = acc[6] * cinv + b1.z; o[7] = acc[7] * cinv + b1.w;
    #pragma unroll
    for (int q = 0; q < 8; q++) o[q] = o[q] > 0.f ? o[q] : expm1f(o[q]);
    uint4 packed = make_uint4(pack2h(o[0], o[1]), pack2h(o[2], o[3]),
                              pack2h(o[4], o[5]), pack2h(o[6], o[7]));
    *(uint4*)(out + (size_t)n * FTOT + lane * 8) = packed;
}

// ---------------- final layer aggregate (1 head, D=32) ----------------
__global__ void __launch_bounds__(256)
agg1_kernel(const float* __restrict__ feat2, const float* __restrict__ el,
            const float* __restrict__ er, const float* __restrict__ bias,
            float* __restrict__ out, const int* __restrict__ off,
            const int* __restrict__ srcs) {
    int warp = (blockIdx.x * blockDim.x + threadIdx.x) >> 5;
    if (warp >= NN) return;
    const int lane = threadIdx.x & 31;
    const int n = warp;
    const int s = off[n], epnd = off[n + 1];
    const float er_n = er[n];

    float mx = -INFINITY, sm = 0.f;
    for (int i = s + lane; i < epnd; i += 32) {
        int src = srcs[i];
        float v = el[src] + er_n;
        v = v > 0.f ? v : 0.2f * v;
        float m2 = fmaxf(mx, v);
        sm = sm * safe_exp(mx - m2) + safe_exp(v - m2);
        mx = m2;
    }
    #pragma unroll
    for (int d = 16; d >= 1; d >>= 1) {
        float om = __shfl_xor_sync(0xffffffffu, mx, d);
        float os = __shfl_xor_sync(0xffffffffu, sm, d);
        float m2 = fmaxf(mx, om);
        sm = sm * safe_exp(mx - m2) + os * safe_exp(om - m2);
        mx = m2;
    }
    const float inv = 1.0f / (sm + 1e-9f);

    float acc = 0.f;
    for (int i = s; i < epnd; i++) {
        int src = srcs[i];
        float v = el[src] + er_n;
        v = v > 0.f ? v : 0.2f * v;
        float coef = safe_exp(v - mx) * inv;
        acc = fmaf(coef, feat2[(size_t)src * HIDD + lane], acc);
    }
    out[(size_t)n * HIDD + lane] = acc + bias[lane];
}

// ---------------- launch ----------------
extern "C" void kernel_launch(void* const* d_in, const int* in_sizes, int n_in,
                              void* d_out, int out_size) {
    const float* features = (const float*)d_in[0];
    const int*   src      = (const int*)d_in[1];
    const int*   dst      = (const int*)d_in[2];
    const float* W0  = (const float*)d_in[3];
    const float* al0 = (const float*)d_in[4];
    const float* ar0 = (const float*)d_in[5];
    const float* b0  = (const float*)d_in[6];
    const float* W1  = (const float*)d_in[7];
    const float* al1 = (const float*)d_in[8];
    const float* ar1 = (const float*)d_in[9];
    const float* b1  = (const float*)d_in[10];
    const float* W2  = (const float*)d_in[11];
    const float* al2 = (const float*)d_in[12];
    const float* ar2 = (const float*)d_in[13];
    const float* b2  = (const float*)d_in[14];
    float* out = (float*)d_out;

    __half *featA, *featB, *hH, *WH, *W2H;
    float *feat2, *elA, *erA, *elB, *erB;
    int *count, *off, *cursor, *srcs, *bsum, *boff;
    cudaGetSymbolAddress((void**)&featA,  g_featA);
    cudaGetSymbolAddress((void**)&featB,  g_featB);
    cudaGetSymbolAddress((void**)&hH,     g_hH);
    cudaGetSymbolAddress((void**)&WH,     g_WH);
    cudaGetSymbolAddress((void**)&W2H,    g_W2H);
    cudaGetSymbolAddress((void**)&feat2,  g_feat2);
    cudaGetSymbolAddress((void**)&elA,    g_elA);
    cudaGetSymbolAddress((void**)&erA,    g_erA);
    cudaGetSymbolAddress((void**)&elB,    g_elB);
    cudaGetSymbolAddress((void**)&erB,    g_erB);
    cudaGetSymbolAddress((void**)&count,  g_count);
    cudaGetSymbolAddress((void**)&off,    g_off);
    cudaGetSymbolAddress((void**)&cursor, g_cursor);
    cudaGetSymbolAddress((void**)&srcs,   g_srcs);
    cudaGetSymbolAddress((void**)&bsum,   g_bsum);
    cudaGetSymbolAddress((void**)&boff,   g_boff);
    __half* WH0 = WH;
    __half* WH1 = WH + FTOT * FTOT;

    cudaFuncSetAttribute(mma_gemm_kernel<float>,
                         cudaFuncAttributeMaxDynamicSharedMemorySize, GEMM_SMEM);
    cudaFuncSetAttribute(mma_gemm_kernel<__half>,
                         cudaFuncAttributeMaxDynamicSharedMemorySize, GEMM_SMEM);
    cudaFuncSetAttribute(mma_final_kernel,
                         cudaFuncAttributeMaxDynamicSharedMemorySize, FGEMM_SMEM);

    static cudaStream_t s2 = nullptr;
    static cudaEvent_t evFork = nullptr, evJoin = nullptr;
    static cudaEvent_t evA = nullptr, evB = nullptr, evC = nullptr, evD = nullptr;
    if (s2 == nullptr) {
        cudaStreamCreateWithFlags(&s2, cudaStreamNonBlocking);
        cudaEventCreateWithFlags(&evFork, cudaEventDisableTiming);
        cudaEventCreateWithFlags(&evJoin, cudaEventDisableTiming);
        cudaEventCreateWithFlags(&evA, cudaEventDisableTiming);
        cudaEventCreateWithFlags(&evB, cudaEventDisableTiming);
        cudaEventCreateWithFlags(&evC, cudaEventDisableTiming);
        cudaEventCreateWithFlags(&evD, cudaEventDisableTiming);
    }

    const int M1 = M1SPLIT;
    const int M2 = NN - M1;
    const int aggBlocksA = (M1 * 32 + 255) / 256;
    const int aggBlocksB = (M2 * 32 + 255) / 256;
    const int aggBlocks  = (NN * 32 + 255) / 256;
    dim3 gemmGridFull(2, (NN + 127) / 128);
    dim3 gemmGridA(2, (M1 + 127) / 128);
    dim3 gemmGridB(2, (M2 + 127) / 128);
    dim3 finalGridA(1, (M1 + 255) / 256);
    dim3 finalGridB(1, (M2 + 255) / 256);

    // fork: CSR build on s2 concurrent with weight prep + GEMM0
    cudaEventRecord(evFork, 0);
    cudaStreamWaitEvent(s2, evFork, 0);
    cudaMemsetAsync(count, 0, NN * sizeof(int), s2);
    hist_kernel<<<(EE + 255) / 256, 256, 0, s2>>>(dst, count);
    scan1_kernel<<<NB, 1024, 0, s2>>>(count, off, bsum);
    scan2_kernel<<<1, 64, 0, s2>>>(bsum, boff, off);
    scan3_kernel<<<NB, 1024, 0, s2>>>(off, boff, cursor);
    scatter_kernel<<<(EE + 255) / 256, 256, 0, s2>>>(dst, src, cursor, srcs);
    cudaEventRecord(evJoin, s2);

    // stream 0: weight prep + GEMM0 (full)
    wtrans_kernel<<<FTOT, FTOT>>>(W0, WH0);
    wtrans_kernel<<<FTOT, FTOT>>>(W1, WH1);
    wtrans2_kernel<<<HIDD, FTOT>>>(W2, W2H);
    mma_gemm_kernel<float><<<gemmGridFull, 256, GEMM_SMEM>>>(features, WH0, featA, al0, ar0, elA, erA, NN);

    // layer 0 aggregate, split halves; GEMM1 pipelined per half
    cudaStreamWaitEvent(0, evJoin, 0);
    agg8_kernel<<<aggBlocksA, 256>>>(featA, elA, erA, b0, hH, off, srcs, 0, M1);
    cudaEventRecord(evA, 0);
    cudaStreamWaitEvent(s2, evA, 0);
    agg8_kernel<<<aggBlocksB, 256, 0, s2>>>(featA, elA, erA, b0, hH, off, srcs, M1, M2);
    mma_gemm_kernel<__half><<<gemmGridA, 256, GEMM_SMEM>>>(hH, WH1, featB, al1, ar1, elB, erB, M1);
    mma_gemm_kernel<__half><<<gemmGridB, 256, GEMM_SMEM, s2>>>(
        hH + (size_t)M1 * FTOT, WH1, featB + (size_t)M1 * FTOT, al1, ar1,
        elB + M1 * NHEADS, erB + M1 * NHEADS, M2);
    cudaEventRecord(evB, s2);

    // layer 1 aggregate, split halves; final GEMM pipelined per half
    cudaStreamWaitEvent(0, evB, 0);
    agg8_kernel<<<aggBlocksA, 256>>>(featB, elB, erB, b1, hH, off, srcs, 0, M1);
    cudaEventRecord(evC, 0);
    cudaStreamWaitEvent(s2, evC, 0);
    agg8_kernel<<<aggBlocksB, 256, 0, s2>>>(featB, elB, erB, b1, hH, off, srcs, M1, M2);
    mma_final_kernel<<<finalGridA, 256, FGEMM_SMEM>>>(hH, W2H, feat2, al2, ar2, elA, erA, M1);
    mma_final_kernel<<<finalGridB, 256, FGEMM_SMEM, s2>>>(
        hH + (size_t)M1 * FTOT, W2H, feat2 + (size_t)M1 * HIDD, al2, ar2,
        elA + M1, erA + M1, M2);
    cudaEventRecord(evD, s2);

    // final aggregate (needs all of feat2 + elA/erA)
    cudaStreamWaitEvent(0, evD, 0);
    agg1_kernel<<<aggBlocks, 256>>>(feat2, elA, erA, b2, out, off, srcs);
}

// round 16
// speedup vs baseline: 1.0181x; 1.0181x over previous
#include <cuda_runtime.h>
#include <cuda_fp16.h>
#include <math.h>
#include <stdint.h>

#define NN 50000
#define EE 800000
#define NHEADS 8
#define HIDD 32
#define FTOT 256   // NHEADS*HIDD, also IN_FEATS
#define NB 49      // scan blocks: 49*1024 >= NN

// ---------------- scratch (static device globals; no allocation) ----------------
__device__ __align__(16) __half g_featH[(size_t)NN * FTOT];  // GEMM out (fp16)
__device__ __align__(16) __half g_hH[(size_t)NN * FTOT];     // agg8 out (fp16)
__device__ __align__(16) __half g_WH[2][FTOT * FTOT];        // W0/W1 transposed fp16
__device__ __align__(16) __half g_W2H[HIDD * FTOT];          // W2 transposed fp16
__device__ __align__(16) __half g_feat2[(size_t)NN * HIDD];  // final GEMM out (fp16)
__device__ __align__(16) float g_el[NN * NHEADS];
__device__ __align__(16) float g_er[NN * NHEADS];
__device__ int g_count[NN];
__device__ int g_off[NN + 1];
__device__ int g_cursor[NN];
__device__ int g_srcs[EE];
__device__ int g_bsum[64];
__device__ int g_boff[64];

// ---------------- helpers ----------------
__device__ __forceinline__ uint32_t smem_u32(const void* p) {
    uint32_t a;
    asm("{ .reg .u64 t; cvta.to.shared.u64 t, %1; cvt.u32.u64 %0, t; }" : "=r"(a) : "l"(p));
    return a;
}
__device__ __forceinline__ void ldsm_x4(uint32_t addr, uint32_t& r0, uint32_t& r1,
                                        uint32_t& r2, uint32_t& r3) {
    asm volatile("ldmatrix.sync.aligned.m8n8.x4.shared.b16 {%0,%1,%2,%3}, [%4];"
                 : "=r"(r0), "=r"(r1), "=r"(r2), "=r"(r3) : "r"(addr));
}
__device__ __forceinline__ void mma_f16(float* d, const uint32_t* a, const uint32_t* b) {
    asm volatile(
        "mma.sync.aligned.m16n8k16.row.col.f32.f16.f16.f32 "
        "{%0,%1,%2,%3}, {%4,%5,%6,%7}, {%8,%9}, {%0,%1,%2,%3};"
        : "+f"(d[0]), "+f"(d[1]), "+f"(d[2]), "+f"(d[3])
        : "r"(a[0]), "r"(a[1]), "r"(a[2]), "r"(a[3]), "r"(b[0]), "r"(b[1]));
}
__device__ __forceinline__ uint32_t pack2h(float a, float b) {
    __half2 t = __floats2half2_rn(a, b);
    return *(uint32_t*)&t;
}
// exp argument guard: fmaxf(NaN, -88) = -88, so (-inf) - (-inf) merges stay finite
__device__ __forceinline__ float safe_exp(float x) {
    return __expf(fmaxf(x, -88.f));
}
__device__ __forceinline__ void loadA16(const float* p, uint32_t* d) {
    const float4* q = (const float4*)p;
    #pragma unroll
    for (int i = 0; i < 4; i++) {
        float4 v = q[i];
        d[2 * i]     = pack2h(v.x, v.y);
        d[2 * i + 1] = pack2h(v.z, v.w);
    }
}
__device__ __forceinline__ void loadA16(const __half* p, uint32_t* d) {
    uint4 a = ((const uint4*)p)[0];
    uint4 b = ((const uint4*)p)[1];
    d[0] = a.x; d[1] = a.y; d[2] = a.z; d[3] = a.w;
    d[4] = b.x; d[5] = b.y; d[6] = b.z; d[7] = b.w;
}
__device__ __forceinline__ void zeroA16(uint32_t* d) {
    #pragma unroll
    for (int q = 0; q < 8; q++) d[q] = 0u;
}

// ---------------- W transposes ----------------
__global__ void wtrans_kernel(const float* __restrict__ W, __half* __restrict__ Wt) {
    int n = blockIdx.x;
    int k = threadIdx.x;
    Wt[n * FTOT + k] = __float2half(W[(size_t)k * FTOT + n]);
}
__global__ void wtrans2_kernel(const float* __restrict__ W2, __half* __restrict__ W2t) {
    int n = blockIdx.x;
    int k = threadIdx.x;
    W2t[n * FTOT + k] = __float2half(W2[(size_t)k * HIDD + n]);
}

// ---------------- mma.sync fp16 GEMM: C[M x 256] = A[M x 256] * Wt^T ----------------
#define SP 40
#define TILE_H (128 * SP)
#define BUF_H (2 * TILE_H)
#define GEMM_SMEM (2 * BUF_H * 2)

template <typename TA>
__global__ void __launch_bounds__(256, 2)
mma_gemm_kernel(const TA* __restrict__ A, const __half* __restrict__ Wt,
                __half* __restrict__ C, const float* __restrict__ al,
                const float* __restrict__ ar, float* __restrict__ el,
                float* __restrict__ er, int M) {
    extern __shared__ __half2 smem_raw[];
    uint16_t* smem = (uint16_t*)smem_raw;
    const int tid = threadIdx.x;
    const int wid = tid >> 5;
    const int lane = tid & 31;
    const int rowBase = blockIdx.y * 128;
    const int colBase = blockIdx.x * 128;
    const int mbase = (wid >> 2) * 64;
    const int nbase = (wid & 3) * 32;

    float acc[4][4][4];
    #pragma unroll
    for (int i = 0; i < 4; i++)
        #pragma unroll
        for (int j = 0; j < 4; j++)
            #pragma unroll
            for (int q = 0; q < 4; q++) acc[i][j][q] = 0.f;

    const int arow = tid >> 1;
    const int akq  = (tid & 1) * 4;
    const __half* Brow = Wt + (size_t)(colBase + arow) * FTOT;

    uint32_t prawA[8], prawB[8];
    {
        int gr = rowBase + arow;
        if (gr < M) loadA16(A + (size_t)gr * FTOT + akq * 4, prawA);
        else zeroA16(prawA);
        loadA16(Brow + akq * 4, prawB);
    }

    for (int c = 0; c < 8; c++) {
        const int b = c & 1;
        uint16_t* As = smem + b * BUF_H;
        uint16_t* Bs = As + TILE_H;

        {
            uint4* da = (uint4*)(As + arow * SP + akq * 4);
            da[0] = make_uint4(prawA[0], prawA[1], prawA[2], prawA[3]);
            da[1] = make_uint4(prawA[4], prawA[5], prawA[6], prawA[7]);
            uint4* db = (uint4*)(Bs + arow * SP + akq * 4);
            db[0] = make_uint4(prawB[0], prawB[1], prawB[2], prawB[3]);
            db[1] = make_uint4(prawB[4], prawB[5], prawB[6], prawB[7]);
        }

        if (c < 7) {
            int gr = rowBase + arow;
            if (gr < M) loadA16(A + (size_t)gr * FTOT + (c + 1) * 32 + akq * 4, prawA);
            else zeroA16(prawA);
            loadA16(Brow + (c + 1) * 32 + akq * 4, prawB);
        }
        __syncthreads();

        const uint32_t as = smem_u32(As);
        const uint32_t bs = smem_u32(Bs);
        const int t = lane >> 3, r = lane & 7;
        #pragma unroll
        for (int ks = 0; ks < 2; ks++) {
            uint32_t Ah[4][4], Bh[4][2];
            const int a_row_off = (t & 1) * 8 + r;
            const int a_col = ks * 16 + (t >> 1) * 8;
            #pragma unroll
            for (int f = 0; f < 4; f++) {
                uint32_t off = ((mbase + f * 16 + a_row_off) * SP + a_col) * 2;
                ldsm_x4(as + off, Ah[f][0], Ah[f][1], Ah[f][2], Ah[f][3]);
            }
            const int b_row_off = (t >> 1) * 8 + r;
            const int b_col = ks * 16 + (t & 1) * 8;
            #pragma unroll
            for (int g = 0; g < 2; g++) {
                uint32_t off = ((nbase + g * 16 + b_row_off) * SP + b_col) * 2;
                ldsm_x4(bs + off, Bh[2 * g][0], Bh[2 * g][1], Bh[2 * g + 1][0], Bh[2 * g + 1][1]);
            }
            #pragma unroll
            for (int i = 0; i < 4; i++)
                #pragma unroll
                for (int j = 0; j < 4; j++)
                    mma_f16(acc[i][j], Ah[i], Bh[j]);
        }
    }

    const int rq = lane >> 2;
    const int cq = (lane & 3) * 2;
    const int hIdx = (colBase >> 5) + (wid & 3);
    float alv[4][2], arv[4][2];
    #pragma unroll
    for (int j = 0; j < 4; j++) {
        int d0 = hIdx * HIDD + j * 8 + cq;
        alv[j][0] = al[d0]; alv[j][1] = al[d0 + 1];
        arv[j][0] = ar[d0]; arv[j][1] = ar[d0 + 1];
    }
    #pragma unroll
    for (int i = 0; i < 4; i++) {
        int r0 = rowBase + mbase + i * 16 + rq;
        int r1 = r0 + 8;
        float sl0 = 0.f, sr0 = 0.f, sl1 = 0.f, sr1 = 0.f;
        #pragma unroll
        for (int j = 0; j < 4; j++) {
            int cc = colBase + nbase + j * 8 + cq;
            if (r0 < M) *(uint32_t*)(C + (size_t)r0 * FTOT + cc) = pack2h(acc[i][j][0], acc[i][j][1]);
            if (r1 < M) *(uint32_t*)(C + (size_t)r1 * FTOT + cc) = pack2h(acc[i][j][2], acc[i][j][3]);
            sl0 = fmaf(acc[i][j][0], alv[j][0], fmaf(acc[i][j][1], alv[j][1], sl0));
            sr0 = fmaf(acc[i][j][0], arv[j][0], fmaf(acc[i][j][1], arv[j][1], sr0));
            sl1 = fmaf(acc[i][j][2], alv[j][0], fmaf(acc[i][j][3], alv[j][1], sl1));
            sr1 = fmaf(acc[i][j][2], arv[j][0], fmaf(acc[i][j][3], arv[j][1], sr1));
        }
        #pragma unroll
        for (int d = 1; d <= 2; d <<= 1) {
            sl0 += __shfl_xor_sync(0xffffffffu, sl0, d);
            sr0 += __shfl_xor_sync(0xffffffffu, sr0, d);
            sl1 += __shfl_xor_sync(0xffffffffu, sl1, d);
            sr1 += __shfl_xor_sync(0xffffffffu, sr1, d);
        }
        if ((lane & 3) == 0) {
            if (r0 < M) { el[r0 * NHEADS + hIdx] = sl0; er[r0 * NHEADS + hIdx] = sr0; }
            if (r1 < M) { el[r1 * NHEADS + hIdx] = sl1; er[r1 * NHEADS + hIdx] = sr1; }
        }
    }
}

// ---------------- final-layer mma GEMM: C[M x 32] (fp16 out) ----------------
#define FSP 40
#define FA_H (256 * FSP)
#define FB_H (32 * FSP)
#define FBUF_H (FA_H + FB_H)
#define FGEMM_SMEM (2 * FBUF_H * 2)

__global__ void __launch_bounds__(256, 2)
mma_final_kernel(const __half* __restrict__ A, const __half* __restrict__ W2t,
                 __half* __restrict__ C, const float* __restrict__ al,
                 const float* __restrict__ ar, float* __restrict__ el,
                 float* __restrict__ er, int M) {
    extern __shared__ __half2 smem_raw[];
    uint16_t* smem = (uint16_t*)smem_raw;
    const int tid = threadIdx.x;
    const int wid = tid >> 5;
    const int lane = tid & 31;
    const int rowBase = blockIdx.y * 256;
    const int mbase = wid * 32;

    float acc[2][4][4];
    #pragma unroll
    for (int i = 0; i < 2; i++)
        #pragma unroll
        for (int j = 0; j < 4; j++)
            #pragma unroll
            for (int q = 0; q < 4; q++) acc[i][j][q] = 0.f;

    const int brow = tid >> 1;
    const int bsl  = (tid & 1) * 16;

    uint32_t prawA[16], prawB[8];
    {
        int gr = rowBase + tid;
        if (gr < M) {
            loadA16(A + (size_t)gr * FTOT, prawA);
            loadA16(A + (size_t)gr * FTOT + 16, prawA + 8);
        } else { zeroA16(prawA); zeroA16(prawA + 8); }
        if (tid < 64) loadA16(W2t + (size_t)brow * FTOT + bsl, prawB);
    }

    for (int c = 0; c < 8; c++) {
        const int b = c & 1;
        uint16_t* As = smem + b * FBUF_H;
        uint16_t* Bs = As + FA_H;

        {
            uint4* da = (uint4*)(As + tid * FSP);
            da[0] = make_uint4(prawA[0], prawA[1], prawA[2], prawA[3]);
            da[1] = make_uint4(prawA[4], prawA[5], prawA[6], prawA[7]);
            da[2] = make_uint4(prawA[8], prawA[9], prawA[10], prawA[11]);
            da[3] = make_uint4(prawA[12], prawA[13], prawA[14], prawA[15]);
            if (tid < 64) {
                uint4* db = (uint4*)(Bs + brow * FSP + bsl);
                db[0] = make_uint4(prawB[0], prawB[1], prawB[2], prawB[3]);
                db[1] = make_uint4(prawB[4], prawB[5], prawB[6], prawB[7]);
            }
        }

        if (c < 7) {
            int gr = rowBase + tid;
            const __half* Ab = A + (size_t)gr * FTOT + (c + 1) * 32;
            if (gr < M) { loadA16(Ab, prawA); loadA16(Ab + 16, prawA + 8); }
            else { zeroA16(prawA); zeroA16(prawA + 8); }
            if (tid < 64) loadA16(W2t + (size_t)brow * FTOT + (c + 1) * 32 + bsl, prawB);
        }
        __syncthreads();

        const uint32_t as = smem_u32(As);
        const uint32_t bs = smem_u32(Bs);
        const int t = lane >> 3, r = lane & 7;
        #pragma unroll
        for (int ks = 0; ks < 2; ks++) {
            uint32_t Ah[2][4], Bh[4][2];
            const int a_row_off = (t & 1) * 8 + r;
            const int a_col = ks * 16 + (t >> 1) * 8;
            #pragma unroll
            for (int f = 0; f < 2; f++) {
                uint32_t off = ((mbase + f * 16 + a_row_off) * FSP + a_col) * 2;
                ldsm_x4(as + off, Ah[f][0], Ah[f][1], Ah[f][2], Ah[f][3]);
            }
            const int b_row_off = (t >> 1) * 8 + r;
            const int b_col = ks * 16 + (t & 1) * 8;
            #pragma unroll
            for (int g = 0; g < 2; g++) {
                uint32_t off = ((g * 16 + b_row_off) * FSP + b_col) * 2;
                ldsm_x4(bs + off, Bh[2 * g][0], Bh[2 * g][1], Bh[2 * g + 1][0], Bh[2 * g + 1][1]);
            }
            #pragma unroll
            for (int i = 0; i < 2; i++)
                #pragma unroll
                for (int j = 0; j < 4; j++)
                    mma_f16(acc[i][j], Ah[i], Bh[j]);
        }
    }

    const int rq = lane >> 2;
    const int cq = (lane & 3) * 2;
    float alv[4][2], arv[4][2];
    #pragma unroll
    for (int j = 0; j < 4; j++) {
        int d0 = j * 8 + cq;
        alv[j][0] = al[d0]; alv[j][1] = al[d0 + 1];
        arv[j][0] = ar[d0]; arv[j][1] = ar[d0 + 1];
    }
    #pragma unroll
    for (int i = 0; i < 2; i++) {
        int r0 = rowBase + mbase + i * 16 + rq;
        int r1 = r0 + 8;
        float sl0 = 0.f, sr0 = 0.f, sl1 = 0.f, sr1 = 0.f;
        #pragma unroll
        for (int j = 0; j < 4; j++) {
            int cc = j * 8 + cq;
            if (r0 < M) *(uint32_t*)(C + (size_t)r0 * HIDD + cc) = pack2h(acc[i][j][0], acc[i][j][1]);
            if (r1 < M) *(uint32_t*)(C + (size_t)r1 * HIDD + cc) = pack2h(acc[i][j][2], acc[i][j][3]);
            sl0 = fmaf(acc[i][j][0], alv[j][0], fmaf(acc[i][j][1], alv[j][1], sl0));
            sr0 = fmaf(acc[i][j][0], arv[j][0], fmaf(acc[i][j][1], arv[j][1], sr0));
            sl1 = fmaf(acc[i][j][2], alv[j][0], fmaf(acc[i][j][3], alv[j][1], sl1));
            sr1 = fmaf(acc[i][j][2], arv[j][0], fmaf(acc[i][j][3], arv[j][1], sr1));
        }
        #pragma unroll
        for (int d = 1; d <= 2; d <<= 1) {
            sl0 += __shfl_xor_sync(0xffffffffu, sl0, d);
            sr0 += __shfl_xor_sync(0xffffffffu, sr0, d);
            sl1 += __shfl_xor_sync(0xffffffffu, sl1, d);
            sr1 += __shfl_xor_sync(0xffffffffu, sr1, d);
        }
        if ((lane & 3) == 0) {
            if (r0 < M) { el[r0] = sl0; er[r0] = sr0; }
            if (r1 < M) { el[r1] = sl1; er[r1] = sr1; }
        }
    }
}

// ---------------- CSR build ----------------
__global__ void hist_kernel(const int* __restrict__ dst, int* __restrict__ count) {
    int e = blockIdx.x * blockDim.x + threadIdx.x;
    if (e < EE) atomicAdd(&count[dst[e]], 1);
}

__global__ void scan1_kernel(const int* __restrict__ count, int* __restrict__ off,
                             int* __restrict__ bsum) {
    __shared__ int wsum[32];
    const int t = threadIdx.x;
    const int lane = t & 31, w = t >> 5;
    const int i = blockIdx.x * 1024 + t;
    int v = (i < NN) ? count[i] : 0;
    int incl = v;
    #pragma unroll
    for (int d = 1; d < 32; d <<= 1) {
        int x = __shfl_up_sync(0xffffffffu, incl, d);
        if (lane >= d) incl += x;
    }
    if (lane == 31) wsum[w] = incl;
    __syncthreads();
    if (w == 0) {
        int s = wsum[lane];
        #pragma unroll
        for (int d = 1; d < 32; d <<= 1) {
            int x = __shfl_up_sync(0xffffffffu, s, d);
            if (lane >= d) s += x;
        }
        wsum[lane] = s;
    }
    __syncthreads();
    int wpre = (w > 0) ? wsum[w - 1] : 0;
    if (i < NN) off[i] = wpre + incl - v;
    if (t == 0) bsum[blockIdx.x] = wsum[31];
}

__global__ void scan2_kernel(const int* __restrict__ bsum, int* __restrict__ boff,
                             int* __restrict__ off) {
    __shared__ int tmp[64];
    int t = threadIdx.x;
    int v = (t < NB) ? bsum[t] : 0;
    tmp[t] = v;
    __syncthreads();
    #pragma unroll
    for (int d = 1; d < 64; d <<= 1) {
        int x = (t >= d) ? tmp[t - d] : 0;
        __syncthreads();
        tmp[t] += x;
        __syncthreads();
    }
    if (t < NB) boff[t] = tmp[t] - v;
    if (t == 63) off[NN] = tmp[63];
}

__global__ void scan3_kernel(int* __restrict__ off, const int* __restrict__ boff,
                             int* __restrict__ cursor) {
    const int i = blockIdx.x * 1024 + threadIdx.x;
    if (i < NN) {
        int o = off[i] + boff[blockIdx.x];
        off[i] = o;
        cursor[i] = o;
    }
}

__global__ void scatter_kernel(const int* __restrict__ dst, const int* __restrict__ srcArr,
                               int* __restrict__ cursor, int* __restrict__ srcs) {
    int e = blockIdx.x * blockDim.x + threadIdx.x;
    if (e < EE) {
        int pos = atomicAdd(&cursor[dst[e]], 1);
        srcs[pos] = srcArr[e];
    }
}

// ---------------- per-node warp: SINGLE-PASS flash-style softmax + aggregate
__global__ void __launch_bounds__(256)
agg8_kernel(const __half* __restrict__ feat, const float* __restrict__ el,
            const float* __restrict__ er, const float* __restrict__ bias,
            __half* __restrict__ out, const int* __restrict__ off,
            const int* __restrict__ srcs) {
    int warp = (blockIdx.x * blockDim.x + threadIdx.x) >> 5;
    if (warp >= NN) return;
    const int lane = threadIdx.x & 31;
    const int n = warp;
    const int s = off[n], epnd = off[n + 1];
    const int hl = lane & 7;
    const int eslot = lane >> 3;
    const int myh = lane >> 2;
    const float er_h = er[n * NHEADS + hl];
    const __half* fbase = feat + lane * 8;

    float mx = -INFINITY;
    float sm = 0.f;
    float acc[8];
    #pragma unroll
    for (int q = 0; q < 8; q++) acc[q] = 0.f;

    int i = s;
    for (; i + 8 <= epnd; i += 8) {
        int s0 = srcs[i + eslot];
        int s1 = srcs[i + 4 + eslot];
        float v0 = el[s0 * NHEADS + hl] + er_h;
        float v1 = el[s1 * NHEADS + hl] + er_h;
        v0 = v0 > 0.f ? v0 : 0.2f * v0;
        v1 = v1 > 0.f ? v1 : 0.2f * v1;
        float bm = fmaxf(v0, v1);
        bm = fmaxf(bm, __shfl_xor_sync(0xffffffffu, bm, 8));
        bm = fmaxf(bm, __shfl_xor_sync(0xffffffffu, bm, 16));
        float m2 = fmaxf(mx, bm);
        float scale = safe_exp(mx - m2);
        float c0 = safe_exp(v0 - m2);
        float c1 = safe_exp(v1 - m2);
        sm = sm * scale + c0 + c1;
        mx = m2;
        float cs = __shfl_sync(0xffffffffu, scale, myh);
        float c[8]; int se[8];
        #pragma unroll
        for (int e = 0; e < 4; e++) {
            c[e]      = __shfl_sync(0xffffffffu, c0, e * 8 + myh);
            c[e + 4]  = __shfl_sync(0xffffffffu, c1, e * 8 + myh);
            se[e]     = __shfl_sync(0xffffffffu, s0, e * 8);
            se[e + 4] = __shfl_sync(0xffffffffu, s1, e * 8);
        }
        uint4 raw[8];
        #pragma unroll
        for (int e = 0; e < 8; e++)
            raw[e] = *(const uint4*)(fbase + (size_t)se[e] * FTOT);
        #pragma unroll
        for (int q = 0; q < 8; q++) acc[q] *= cs;
        #pragma unroll
        for (int e = 0; e < 8; e++) {
            const __half2* hp = (const __half2*)&raw[e];
            #pragma unroll
            for (int q = 0; q < 4; q++) {
                float2 f = __half22float2(hp[q]);
                acc[q * 2]     = fmaf(c[e], f.x, acc[q * 2]);
                acc[q * 2 + 1] = fmaf(c[e], f.y, acc[q * 2 + 1]);
            }
        }
    }
    for (; i + 4 <= epnd; i += 4) {
        int esrc = srcs[i + eslot];
        float v = el[esrc * NHEADS + hl] + er_h;
        v = v > 0.f ? v : 0.2f * v;
        float bm = v;
        bm = fmaxf(bm, __shfl_xor_sync(0xffffffffu, bm, 8));
        bm = fmaxf(bm, __shfl_xor_sync(0xffffffffu, bm, 16));
        float m2 = fmaxf(mx, bm);
        float scale = safe_exp(mx - m2);
        float coef = safe_exp(v - m2);
        sm = sm * scale + coef;
        mx = m2;
        float cs = __shfl_sync(0xffffffffu, scale, myh);
        float c[4]; int se[4];
        #pragma unroll
        for (int e = 0; e < 4; e++) {
            c[e]  = __shfl_sync(0xffffffffu, coef, e * 8 + myh);
            se[e] = __shfl_sync(0xffffffffu, esrc, e * 8);
        }
        uint4 raw[4];
        #pragma unroll
        for (int e = 0; e < 4; e++)
            raw[e] = *(const uint4*)(fbase + (size_t)se[e] * FTOT);
        #pragma unroll
        for (int q = 0; q < 8; q++) acc[q] *= cs;
        #pragma unroll
        for (int e = 0; e < 4; e++) {
            const __half2* hp = (const __half2*)&raw[e];
            #pragma unroll
            for (int q = 0; q < 4; q++) {
                float2 f = __half22float2(hp[q]);
                acc[q * 2]     = fmaf(c[e], f.x, acc[q * 2]);
                acc[q * 2 + 1] = fmaf(c[e], f.y, acc[q * 2 + 1]);
            }
        }
    }
    for (; i < epnd; i++) {
        int srcT = srcs[i];
        float v = el[srcT * NHEADS + hl] + er_h;
        v = v > 0.f ? v : 0.2f * v;
        float m2 = fmaxf(mx, v);
        float scale = safe_exp(mx - m2);
        float coef = safe_exp(v - m2);
        sm = sm * scale + (eslot == 0 ? coef : 0.f);
        mx = m2;
        float cs = __shfl_sync(0xffffffffu, scale, myh);
        float c  = __shfl_sync(0xffffffffu, coef, myh);
        uint4 raw = *(const uint4*)(fbase + (size_t)srcT * FTOT);
        const __half2* hp = (const __half2*)&raw;
        #pragma unroll
        for (int q = 0; q < 8; q++) acc[q] *= cs;
        #pragma unroll
        for (int q = 0; q < 4; q++) {
            float2 f = __half22float2(hp[q]);
            acc[q * 2]     = fmaf(c, f.x, acc[q * 2]);
            acc[q * 2 + 1] = fmaf(c, f.y, acc[q * 2 + 1]);
        }
    }
    sm += __shfl_xor_sync(0xffffffffu, sm, 8);
    sm += __shfl_xor_sync(0xffffffffu, sm, 16);
    float inv = 1.0f / (sm + 1e-9f);
    float cinv = __shfl_sync(0xffffffffu, inv, myh);
    float4 b0 = *(const float4*)(bias + lane * 8);
    float4 b1 = *(const float4*)(bias + lane * 8 + 4);
    float o[8];
    o[0] = acc[0] * cinv + b0.x; o[1] = acc[1] * cinv + b0.y;
    o[2] = acc[2] * cinv + b0.z; o[3] = acc[3] * cinv + b0.w;
    o[4] = acc[4] * cinv + b1.x; o[5] = acc[5] * cinv + b1.y;
    o[6] = acc[6] * cinv + b1.z; o[7] = acc[7] * cinv + b1.w;
    #pragma unroll
    for (int q = 0; q < 8; q++) o[q] = o[q] > 0.f ? o[q] : expm1f(o[q]);
    uint4 packed = make_uint4(pack2h(o[0], o[1]), pack2h(o[2], o[3]),
                              pack2h(o[4], o[5]), pack2h(o[6], o[7]));
    *(uint4*)(out + (size_t)n * FTOT + lane * 8) = packed;
}

// ---------------- final layer aggregate (1 head, D=32, fp16 feat2) ----------------
__global__ void __launch_bounds__(256)
agg1_kernel(const __half* __restrict__ feat2, const float* __restrict__ el,
            const float* __restrict__ er, const float* __restrict__ bias,
            float* __restrict__ out, const int* __restrict__ off,
            const int* __restrict__ srcs) {
    int warp = (blockIdx.x * blockDim.x + threadIdx.x) >> 5;
    if (warp >= NN) return;
    const int lane = threadIdx.x & 31;
    const int n = warp;
    const int s = off[n], epnd = off[n + 1];
    const float er_n = er[n];

    float mx = -INFINITY, sm = 0.f;
    for (int i = s + lane; i < epnd; i += 32) {
        int src = srcs[i];
        float v = el[src] + er_n;
        v = v > 0.f ? v : 0.2f * v;
        float m2 = fmaxf(mx, v);
        sm = sm * safe_exp(mx - m2) + safe_exp(v - m2);
        mx = m2;
    }
    #pragma unroll
    for (int d = 16; d >= 1; d >>= 1) {
        float om = __shfl_xor_sync(0xffffffffu, mx, d);
        float os = __shfl_xor_sync(0xffffffffu, sm, d);
        float m2 = fmaxf(mx, om);
        sm = sm * safe_exp(mx - m2) + os * safe_exp(om - m2);
        mx = m2;
    }
    const float inv = 1.0f / (sm + 1e-9f);

    float acc = 0.f;
    for (int i = s; i < epnd; i++) {
        int src = srcs[i];
        float v = el[src] + er_n;
        v = v > 0.f ? v : 0.2f * v;
        float coef = safe_exp(v - mx) * inv;
        acc = fmaf(coef, __half2float(feat2[(size_t)src * HIDD + lane]), acc);
    }
    out[(size_t)n * HIDD + lane] = acc + bias[lane];
}

// ---------------- launch ----------------
extern "C" void kernel_launch(void* const* d_in, const int* in_sizes, int n_in,
                              void* d_out, int out_size) {
    const float* features = (const float*)d_in[0];
    const int*   src      = (const int*)d_in[1];
    const int*   dst      = (const int*)d_in[2];
    const float* W0  = (const float*)d_in[3];
    const float* al0 = (const float*)d_in[4];
    const float* ar0 = (const float*)d_in[5];
    const float* b0  = (const float*)d_in[6];
    const float* W1  = (const float*)d_in[7];
    const float* al1 = (const float*)d_in[8];
    const float* ar1 = (const float*)d_in[9];
    const float* b1  = (const float*)d_in[10];
    const float* W2  = (const float*)d_in[11];
    const float* al2 = (const float*)d_in[12];
    const float* ar2 = (const float*)d_in[13];
    const float* b2  = (const float*)d_in[14];
    float* out = (float*)d_out;

    __half *featH, *hH, *WH, *W2H, *feat2;
    float *el, *er;
    int *count, *off, *cursor, *srcs, *bsum, *boff;
    cudaGetSymbolAddress((void**)&featH,  g_featH);
    cudaGetSymbolAddress((void**)&hH,     g_hH);
    cudaGetSymbolAddress((void**)&WH,     g_WH);
    cudaGetSymbolAddress((void**)&W2H,    g_W2H);
    cudaGetSymbolAddress((void**)&feat2,  g_feat2);
    cudaGetSymbolAddress((void**)&el,     g_el);
    cudaGetSymbolAddress((void**)&er,     g_er);
    cudaGetSymbolAddress((void**)&count,  g_count);
    cudaGetSymbolAddress((void**)&off,    g_off);
    cudaGetSymbolAddress((void**)&cursor, g_cursor);
    cudaGetSymbolAddress((void**)&srcs,   g_srcs);
    cudaGetSymbolAddress((void**)&bsum,   g_bsum);
    cudaGetSymbolAddress((void**)&boff,   g_boff);
    __half* WH0 = WH;
    __half* WH1 = WH + FTOT * FTOT;

    cudaFuncSetAttribute(mma_gemm_kernel<float>,
                         cudaFuncAttributeMaxDynamicSharedMemorySize, GEMM_SMEM);
    cudaFuncSetAttribute(mma_gemm_kernel<__half>,
                         cudaFuncAttributeMaxDynamicSharedMemorySize, GEMM_SMEM);
    cudaFuncSetAttribute(mma_final_kernel,
                         cudaFuncAttributeMaxDynamicSharedMemorySize, FGEMM_SMEM);

    static cudaStream_t s2 = nullptr;
    static cudaEvent_t evFork = nullptr, evJoin = nullptr;
    if (s2 == nullptr) {
        cudaStreamCreateWithFlags(&s2, cudaStreamNonBlocking);
        cudaEventCreateWithFlags(&evFork, cudaEventDisableTiming);
        cudaEventCreateWithFlags(&evJoin, cudaEventDisableTiming);
    }

    // fork: CSR build + W1/W2 prep on s2 run concurrently with W0 prep + GEMM0.
    // Everything on s2 completes before evJoin; GEMM1/final (consumers of
    // WH1/W2H) launch after the stream-0 wait on evJoin.
    cudaEventRecord(evFork, 0);
    cudaStreamWaitEvent(s2, evFork, 0);
    wtrans_kernel<<<FTOT, FTOT, 0, s2>>>(W1, WH1);
    wtrans2_kernel<<<HIDD, FTOT, 0, s2>>>(W2, W2H);
    cudaMemsetAsync(count, 0, NN * sizeof(int), s2);
    hist_kernel<<<(EE + 255) / 256, 256, 0, s2>>>(dst, count);
    scan1_kernel<<<NB, 1024, 0, s2>>>(count, off, bsum);
    scan2_kernel<<<1, 64, 0, s2>>>(bsum, boff, off);
    scan3_kernel<<<NB, 1024, 0, s2>>>(off, boff, cursor);
    scatter_kernel<<<(EE + 255) / 256, 256, 0, s2>>>(dst, src, cursor, srcs);
    cudaEventRecord(evJoin, s2);

    const int aggBlocks = (NN * 32 + 255) / 256;
    dim3 gemmGrid(2, (NN + 127) / 128);
    dim3 finalGrid(1, (NN + 255) / 256);

    // stream 0: W0 prep + GEMM0
    wtrans_kernel<<<FTOT, FTOT>>>(W0, WH0);
    mma_gemm_kernel<float><<<gemmGrid, 256, GEMM_SMEM>>>(features, WH0, featH, al0, ar0, el, er, NN);

    // join: agg8 needs the CSR (and WH1/W2H become safe to consume)
    cudaStreamWaitEvent(0, evJoin, 0);
    agg8_kernel<<<aggBlocks, 256>>>(featH, el, er, b0, hH, off, srcs);

    // layer 1
    mma_gemm_kernel<__half><<<gemmGrid, 256, GEMM_SMEM>>>(hH, WH1, featH, al1, ar1, el, er, NN);
    agg8_kernel<<<aggBlocks, 256>>>(featH, el, er, b1, hH, off, srcs);

    // layer 2 (mma, fused el/er, fp16 out)
    mma_final_kernel<<<finalGrid, 256, FGEMM_SMEM>>>(hH, W2H, feat2, al2, ar2, el, er, NN);
    agg1_kernel<<<aggBlocks, 256>>>(feat2, el, er, b2, out, off, srcs);
}